// round 6
// baseline (speedup 1.0000x reference)
#include <cuda_runtime.h>

// WaveletAttention: 3-level Haar DWT -> per-batch scalar gates -> gated IDWT.
// R6: (a) k_recon reverted to R3 shape (4 cols x 8 rows, float4, plain
//     stores) - proven 20.4us; fine-thread float2 variant regressed.
//     (b) k_forward stages weight slabs into smem with coalesced float4
//     streams (fixes 3x sector replay of strided float2 weight loads).
//     (c) no atomics: per-CTA partials reduced in k_gates.

#define HH 1024
#define WW 1024
#define NB 16
#define N1c 262144   // 512*512 per component, weights Wd3 (finest)
#define N2c 65536    // 256*256, weights Wd2
#define N3c 16384    // 128*128, weights Wd1 (coarsest)
#define FWD_BLOCKS 128   // gridDim.x of k_forward

// partials: [pair][20][FWD_BLOCKS]; gates per batch: 10 floats
// [0] approx sigmoid, [1:4] L3 (Wd1), [4:7] L2 (Wd2), [7:10] L1 (Wd3)
__device__ float g_part[(NB / 2) * 20 * FWD_BLOCKS];
__device__ float g_gates[NB * 10];

__device__ __forceinline__ void haar_fwd(float x00, float x01, float x10, float x11,
                                         float& a, float& h, float& v, float& dd) {
    float s0 = x00 + x01, m0 = x00 - x01;
    float s1 = x10 + x11, m1 = x10 - x11;
    a  = 0.5f * (s0 + s1);
    h  = 0.5f * (s0 - s1);
    v  = 0.5f * (m0 + m1);
    dd = 0.5f * (m0 - m1);
}

__device__ __forceinline__ void haar_inv(float a, float h, float v, float dd,
                                         float& x00, float& x01, float& x10, float& x11) {
    float ph = a + h, mh = a - h;
    float pv = v + dd, mv = v - dd;
    x00 = 0.5f * (ph + pv);
    x01 = 0.5f * (ph - pv);
    x10 = 0.5f * (mh + mv);
    x11 = 0.5f * (mh - mv);
}

// ---------------------------------------------------------------------------
// K1: forward DWT + logit partials, TWO batches per thread, smem-staged
// weights. CTA = one row-group r (8 image rows), 256 col-groups of 4 cols.
// grid: (FWD_BLOCKS, NB/2) x 256.
// ---------------------------------------------------------------------------
__global__ void __launch_bounds__(256) k_forward(
    const float* __restrict__ x,
    const float* __restrict__ Wa,
    const float* __restrict__ Wd1,   // [3*N3c, 3] coarsest
    const float* __restrict__ Wd2,   // [3*N2c, 3]
    const float* __restrict__ Wd3)   // [3*N1c, 3] finest
{
    const int b0 = blockIdx.y * 2;
    const int g = threadIdx.x;       // col group (4 cols)
    const int r = blockIdx.x;        // row group (8 rows)
    const size_t off = (size_t)(r * 8) * WW + g * 4;
    const float* xA = x + (size_t)b0 * (HH * WW) + off;
    const float* xB = xA + (size_t)(HH * WW);

    __shared__ float wbuf[4608];     // 18 KB weight stage (reused per stage)

    float saA = 0.f, s1xA = 0.f, s1yA = 0.f, s1zA = 0.f;
    float s2xA = 0.f, s2yA = 0.f, s2zA = 0.f, s3xA = 0.f, s3yA = 0.f, s3zA = 0.f;
    float saB = 0.f, s1xB = 0.f, s1yB = 0.f, s1zB = 0.f;
    float s2xB = 0.f, s2yB = 0.f, s2zB = 0.f, s3xB = 0.f, s3yB = 0.f, s3zB = 0.f;

    float a0A[4], a1A[4], a0B[4], a1B[4];

    // ---- level 1: 4 coefficient rows, weights staged per row ----
    #pragma unroll
    for (int ry = 0; ry < 4; ry++) {
        const int y1 = r * 4 + ry;

        __syncthreads();   // previous stage fully consumed
        // stage 3 x 1536 floats (h,v,d weight rows for 512 coeffs), coalesced
        {
            const float* s0 = Wd3 + (size_t)y1 * 1536;
            #pragma unroll
            for (int c = 0; c < 3; c++) {
                const float4* s = (const float4*)(s0 + (size_t)c * 3 * N1c);
                float4* dst = (float4*)(wbuf + c * 1536);
                dst[g] = s[g];
                if (g < 128) dst[g + 256] = s[g + 256];
            }
        }
        __syncthreads();

        float4 uA = *(const float4*)(xA + (size_t)(2 * ry) * WW);
        float4 wA = *(const float4*)(xA + (size_t)(2 * ry + 1) * WW);
        float4 uB = *(const float4*)(xB + (size_t)(2 * ry) * WW);
        float4 wB = *(const float4*)(xB + (size_t)(2 * ry + 1) * WW);

        const float* bh = wbuf + 0 * 1536 + 6 * g;   // rows 2g, 2g+1: 6 floats
        const float* bv = wbuf + 1 * 1536 + 6 * g;
        const float* bd = wbuf + 2 * 1536 + 6 * g;
        float h00 = bh[0], h01 = bh[1], h02 = bh[2], h10 = bh[3], h11 = bh[4], h12 = bh[5];
        float v00 = bv[0], v01 = bv[1], v02 = bv[2], v10 = bv[3], v11 = bv[4], v12 = bv[5];
        float d00 = bd[0], d01 = bd[1], d02 = bd[2], d10 = bd[3], d11 = bd[4], d12 = bd[5];

        float h0, v0, d0, h1, v1, d1;
        haar_fwd(uA.x, uA.y, wA.x, wA.y, a0A[ry], h0, v0, d0);
        haar_fwd(uA.z, uA.w, wA.z, wA.w, a1A[ry], h1, v1, d1);
        s1xA += h0 * h00 + h1 * h10 + v0 * v00 + v1 * v10 + d0 * d00 + d1 * d10;
        s1yA += h0 * h01 + h1 * h11 + v0 * v01 + v1 * v11 + d0 * d01 + d1 * d11;
        s1zA += h0 * h02 + h1 * h12 + v0 * v02 + v1 * v12 + d0 * d02 + d1 * d12;

        haar_fwd(uB.x, uB.y, wB.x, wB.y, a0B[ry], h0, v0, d0);
        haar_fwd(uB.z, uB.w, wB.z, wB.w, a1B[ry], h1, v1, d1);
        s1xB += h0 * h00 + h1 * h10 + v0 * v00 + v1 * v10 + d0 * d00 + d1 * d10;
        s1yB += h0 * h01 + h1 * h11 + v0 * v01 + v1 * v11 + d0 * d01 + d1 * d11;
        s1zB += h0 * h02 + h1 * h12 + v0 * v02 + v1 * v12 + d0 * d02 + d1 * d12;
    }

    // ---- level 2: 2 coefficient rows, weights staged per row ----
    float a2A[2], a2B[2];
    #pragma unroll
    for (int ry2 = 0; ry2 < 2; ry2++) {
        const int row2 = r * 2 + ry2;

        __syncthreads();
        {
            const float* s0 = Wd2 + (size_t)row2 * 768;
            #pragma unroll
            for (int c = 0; c < 3; c++) {
                const float4* s = (const float4*)(s0 + (size_t)c * 3 * N2c);
                if (g < 192) ((float4*)(wbuf + c * 768))[g] = s[g];
            }
        }
        __syncthreads();

        const float* bh = wbuf + 0 * 768 + 3 * g;
        const float* bv = wbuf + 1 * 768 + 3 * g;
        const float* bd = wbuf + 2 * 768 + 3 * g;
        float w0 = bh[0], w1 = bh[1], w2 = bh[2];
        float w3 = bv[0], w4 = bv[1], w5 = bv[2];
        float w6 = bd[0], w7 = bd[1], w8 = bd[2];

        float h, v, dd;
        haar_fwd(a0A[2*ry2], a1A[2*ry2], a0A[2*ry2+1], a1A[2*ry2+1], a2A[ry2], h, v, dd);
        s2xA += h * w0 + v * w3 + dd * w6;
        s2yA += h * w1 + v * w4 + dd * w7;
        s2zA += h * w2 + v * w5 + dd * w8;

        haar_fwd(a0B[2*ry2], a1B[2*ry2], a0B[2*ry2+1], a1B[2*ry2+1], a2B[ry2], h, v, dd);
        s2xB += h * w0 + v * w3 + dd * w6;
        s2yB += h * w1 + v * w4 + dd * w7;
        s2zB += h * w2 + v * w5 + dd * w8;
    }

    // ---- level 3: combine lane pairs; only even lane accumulates ----
    {
        float pA0 = __shfl_xor_sync(0xFFFFFFFFu, a2A[0], 1);
        float pA1 = __shfl_xor_sync(0xFFFFFFFFu, a2A[1], 1);
        float pB0 = __shfl_xor_sync(0xFFFFFFFFu, a2B[0], 1);
        float pB1 = __shfl_xor_sync(0xFFFFFFFFu, a2B[1], 1);
        if ((g & 1) == 0) {
            const size_t i = (size_t)r * 128 + (g >> 1);
            const float* ph = Wd1 + 3 * i;
            const float* pv = Wd1 + 3 * (N3c + i);
            const float* pd = Wd1 + 3 * (2 * (size_t)N3c + i);
            float w0 = __ldg(ph + 0), w1 = __ldg(ph + 1), w2 = __ldg(ph + 2);
            float w3 = __ldg(pv + 0), w4 = __ldg(pv + 1), w5 = __ldg(pv + 2);
            float w6 = __ldg(pd + 0), w7 = __ldg(pd + 1), w8 = __ldg(pd + 2);
            float wa = __ldg(Wa + i);

            float a, h, v, dd;
            haar_fwd(a2A[0], pA0, a2A[1], pA1, a, h, v, dd);
            s3xA = h * w0 + v * w3 + dd * w6;
            s3yA = h * w1 + v * w4 + dd * w7;
            s3zA = h * w2 + v * w5 + dd * w8;
            saA  = a * wa;

            haar_fwd(a2B[0], pB0, a2B[1], pB1, a, h, v, dd);
            s3xB = h * w0 + v * w3 + dd * w6;
            s3yB = h * w1 + v * w4 + dd * w7;
            s3zB = h * w2 + v * w5 + dd * w8;
            saB  = a * wa;
        }
    }

    // ---- block reduction of 20 scalars -> per-CTA partials ----
    float vals[20] = {saA, s3xA, s3yA, s3zA, s2xA, s2yA, s2zA, s1xA, s1yA, s1zA,
                      saB, s3xB, s3yB, s3zB, s2xB, s2yB, s2zB, s1xB, s1yB, s1zB};
    __shared__ float sm[20][8];
    int lane = threadIdx.x & 31;
    int wid  = threadIdx.x >> 5;
    #pragma unroll
    for (int k = 0; k < 20; k++) {
        float v = vals[k];
        #pragma unroll
        for (int off2 = 16; off2 > 0; off2 >>= 1)
            v += __shfl_down_sync(0xFFFFFFFFu, v, off2);
        if (lane == 0) sm[k][wid] = v;
    }
    __syncthreads();
    if (threadIdx.x < 20) {
        float t = 0.f;
        #pragma unroll
        for (int w = 0; w < 8; w++) t += sm[threadIdx.x][w];
        g_part[(blockIdx.y * 20 + threadIdx.x) * FWD_BLOCKS + blockIdx.x] = t;
    }
}

// ---------------------------------------------------------------------------
// K2: reduce partials + compute gates. grid = NB blocks x 128 threads.
// ---------------------------------------------------------------------------
__global__ void __launch_bounds__(128) k_gates(
    const float* __restrict__ ba,
    const float* __restrict__ bd1,
    const float* __restrict__ bd2,
    const float* __restrict__ bd3)
{
    const int batch = blockIdx.x;
    const int pair = batch >> 1;
    const int sub  = (batch & 1) * 10;
    const int tid = threadIdx.x;
    const int lane = tid & 31;
    const int wid  = tid >> 5;

    __shared__ float red[10];
    __shared__ float wsum[4];

    #pragma unroll
    for (int k = 0; k < 10; k++) {
        float v = g_part[(pair * 20 + sub + k) * FWD_BLOCKS + tid];
        #pragma unroll
        for (int off = 16; off > 0; off >>= 1)
            v += __shfl_down_sync(0xFFFFFFFFu, v, off);
        if (lane == 0) wsum[wid] = v;
        __syncthreads();
        if (tid == 0) red[k] = wsum[0] + wsum[1] + wsum[2] + wsum[3];
        __syncthreads();
    }

    if (tid == 0) {
        float* G = g_gates + batch * 10;
        G[0] = 1.0f / (1.0f + __expf(-(red[0] + ba[0])));
        const float* bds[3] = {bd1, bd2, bd3};
        #pragma unroll
        for (int s = 0; s < 3; s++) {
            float l0 = red[1 + 3*s] + bds[s][0];
            float l1 = red[2 + 3*s] + bds[s][1];
            float l2 = red[3 + 3*s] + bds[s][2];
            float m = fmaxf(fmaxf(l0, l1), l2);
            float e0 = __expf(l0 - m), e1 = __expf(l1 - m), e2 = __expf(l2 - m);
            float inv = 1.0f / (e0 + e1 + e2);
            G[1 + 3*s] = e0 * inv; G[2 + 3*s] = e1 * inv; G[3 + 3*s] = e2 * inv;
        }
    }
}

// ---------------------------------------------------------------------------
// K3: single-pass reconstruct (R3 shape: 4 cols x 8 rows, float4 I/O).
// Level-3 computed symmetrically in both lanes of a pair (shfl_xor 1).
// grid: (128, NB) x 256.
// ---------------------------------------------------------------------------
__global__ void __launch_bounds__(256) k_recon(
    const float* __restrict__ x, float* __restrict__ out)
{
    const int batch = blockIdx.y;
    const int bt = blockIdx.x * blockDim.x + threadIdx.x;
    const int g = bt & 255;
    const int r = bt >> 8;
    const size_t base = (size_t)batch * (HH * WW) + (size_t)(r * 8) * WW + g * 4;
    const float* xb = x + base;
    float* ob = out + base;

    const float* G = g_gates + batch * 10;
    const float aw  = __ldg(G + 0);
    const float g3h = __ldg(G + 1), g3v = __ldg(G + 2), g3d = __ldg(G + 3);
    const float g2h = __ldg(G + 4), g2v = __ldg(G + 5), g2d = __ldg(G + 6);
    const float g1h = __ldg(G + 7), g1v = __ldg(G + 8), g1d = __ldg(G + 9);

    // ---- forward level 1 (store gated details) ----
    float a1_0[4], a1_1[4];
    float h1_0[4], v1_0[4], d1_0[4];
    float h1_1[4], v1_1[4], d1_1[4];
    #pragma unroll
    for (int ry = 0; ry < 4; ry++) {
        float4 u = *(const float4*)(xb + (size_t)(2 * ry) * WW);
        float4 w = *(const float4*)(xb + (size_t)(2 * ry + 1) * WW);
        float h, v, dd;
        haar_fwd(u.x, u.y, w.x, w.y, a1_0[ry], h, v, dd);
        h1_0[ry] = h * g1h; v1_0[ry] = v * g1v; d1_0[ry] = dd * g1d;
        haar_fwd(u.z, u.w, w.z, w.w, a1_1[ry], h, v, dd);
        h1_1[ry] = h * g1h; v1_1[ry] = v * g1v; d1_1[ry] = dd * g1d;
    }

    // ---- forward level 2 (gated) ----
    float a2[2], h2[2], v2[2], d2[2];
    #pragma unroll
    for (int ry2 = 0; ry2 < 2; ry2++) {
        float h, v, dd;
        haar_fwd(a1_0[2*ry2], a1_1[2*ry2], a1_0[2*ry2+1], a1_1[2*ry2+1],
                 a2[ry2], h, v, dd);
        h2[ry2] = h * g2h; v2[ry2] = v * g2v; d2[ry2] = dd * g2d;
    }

    // ---- level 3: symmetric in both lanes of the pair ----
    float R2[2];
    {
        float pa0 = __shfl_xor_sync(0xFFFFFFFFu, a2[0], 1);
        float pa1 = __shfl_xor_sync(0xFFFFFFFFu, a2[1], 1);
        bool odd = (g & 1);
        float lo0 = odd ? pa0 : a2[0], hi0 = odd ? a2[0] : pa0;
        float lo1 = odd ? pa1 : a2[1], hi1 = odd ? a2[1] : pa1;
        float a, h, v, dd;
        haar_fwd(lo0, hi0, lo1, hi1, a, h, v, dd);
        a *= aw; h *= g3h; v *= g3v; dd *= g3d;
        float x00, x01, x10, x11;
        haar_inv(a, h, v, dd, x00, x01, x10, x11);
        R2[0] = odd ? x01 : x00;
        R2[1] = odd ? x11 : x10;
    }

    // ---- inverse level 2 ----
    float r1_0[4], r1_1[4];
    #pragma unroll
    for (int ry2 = 0; ry2 < 2; ry2++) {
        haar_inv(R2[ry2], h2[ry2], v2[ry2], d2[ry2],
                 r1_0[2*ry2], r1_1[2*ry2], r1_0[2*ry2+1], r1_1[2*ry2+1]);
    }

    // ---- inverse level 1 + coalesced float4 stores ----
    #pragma unroll
    for (int ry = 0; ry < 4; ry++) {
        float p00, p01, p10, p11, q00, q01, q10, q11;
        haar_inv(r1_0[ry], h1_0[ry], v1_0[ry], d1_0[ry], p00, p01, p10, p11);
        haar_inv(r1_1[ry], h1_1[ry], v1_1[ry], d1_1[ry], q00, q01, q10, q11);
        *(float4*)(ob + (size_t)(2 * ry) * WW)     = make_float4(p00, p01, q00, q01);
        *(float4*)(ob + (size_t)(2 * ry + 1) * WW) = make_float4(p10, p11, q10, q11);
    }
}

// ---------------------------------------------------------------------------
extern "C" void kernel_launch(void* const* d_in, const int* in_sizes, int n_in,
                              void* d_out, int out_size) {
    const float* x   = (const float*)d_in[0];
    const float* Wa  = (const float*)d_in[1];
    const float* ba  = (const float*)d_in[2];
    const float* Wd1 = (const float*)d_in[3];
    const float* bd1 = (const float*)d_in[4];
    const float* Wd2 = (const float*)d_in[5];
    const float* bd2 = (const float*)d_in[6];
    const float* Wd3 = (const float*)d_in[7];
    const float* bd3 = (const float*)d_in[8];
    float* out = (float*)d_out;

    k_forward<<<dim3(FWD_BLOCKS, NB / 2), 256>>>(x, Wa, Wd1, Wd2, Wd3);
    k_gates<<<NB, 128>>>(ba, bd1, bd2, bd3);
    k_recon<<<dim3(128, NB), 256>>>(x, out);
}

// round 7
// speedup vs baseline: 1.1441x; 1.1441x over previous
#include <cuda_runtime.h>

// WaveletAttention: 3-level Haar DWT -> per-batch scalar gates -> gated IDWT.
// R7: recombination of measured-best parts:
//   k_forward = R5 (2 batches/thread, strided float2 weights, per-CTA
//               partials, no atomics)          -> 22.6us measured
//   k_recon   = R3/R4 (4 cols x 8 rows, float4 I/O, plain stores) -> 20.4us
//   k_gates   = R5 partials reduction
// R6's smem weight staging reverted (regs 90/occ 23%/barrier serialization).

#define HH 1024
#define WW 1024
#define NB 16
#define N1c 262144   // 512*512 per component, weights Wd3 (finest)
#define N2c 65536    // 256*256, weights Wd2
#define N3c 16384    // 128*128, weights Wd1 (coarsest)
#define FWD_BLOCKS 128   // gridDim.x of k_forward

// partials: [pair][20][FWD_BLOCKS]; gates per batch: 10 floats
// [0] approx sigmoid, [1:4] L3 (Wd1), [4:7] L2 (Wd2), [7:10] L1 (Wd3)
__device__ float g_part[(NB / 2) * 20 * FWD_BLOCKS];
__device__ float g_gates[NB * 10];

__device__ __forceinline__ void haar_fwd(float x00, float x01, float x10, float x11,
                                         float& a, float& h, float& v, float& dd) {
    float s0 = x00 + x01, m0 = x00 - x01;
    float s1 = x10 + x11, m1 = x10 - x11;
    a  = 0.5f * (s0 + s1);
    h  = 0.5f * (s0 - s1);
    v  = 0.5f * (m0 + m1);
    dd = 0.5f * (m0 - m1);
}

__device__ __forceinline__ void haar_inv(float a, float h, float v, float dd,
                                         float& x00, float& x01, float& x10, float& x11) {
    float ph = a + h, mh = a - h;
    float pv = v + dd, mv = v - dd;
    x00 = 0.5f * (ph + pv);
    x01 = 0.5f * (ph - pv);
    x10 = 0.5f * (mh + mv);
    x11 = 0.5f * (mh - mv);
}

// ---------------------------------------------------------------------------
// K1: forward DWT + logit partials, TWO batches per thread.
// Thread = col-group g (4 cols) x 8 rows. grid: (FWD_BLOCKS, NB/2) x 256.
// ---------------------------------------------------------------------------
__global__ void __launch_bounds__(256) k_forward(
    const float* __restrict__ x,
    const float* __restrict__ Wa,
    const float* __restrict__ Wd1,   // [3*N3c, 3] coarsest
    const float* __restrict__ Wd2,   // [3*N2c, 3]
    const float* __restrict__ Wd3)   // [3*N1c, 3] finest
{
    const int b0 = blockIdx.y * 2;
    const int bt = blockIdx.x * blockDim.x + threadIdx.x;   // 0..32767
    const int g = bt & 255;
    const int r = bt >> 8;
    const size_t off = (size_t)(r * 8) * WW + g * 4;
    const float* xA = x + (size_t)b0 * (HH * WW) + off;
    const float* xB = xA + (size_t)(HH * WW);

    float saA = 0.f, s1xA = 0.f, s1yA = 0.f, s1zA = 0.f;
    float s2xA = 0.f, s2yA = 0.f, s2zA = 0.f, s3xA = 0.f, s3yA = 0.f, s3zA = 0.f;
    float saB = 0.f, s1xB = 0.f, s1yB = 0.f, s1zB = 0.f;
    float s2xB = 0.f, s2yB = 0.f, s2zB = 0.f, s3xB = 0.f, s3yB = 0.f, s3zB = 0.f;

    float a0A[4], a1A[4], a0B[4], a1B[4];

    // ---- level 1 ----
    #pragma unroll
    for (int ry = 0; ry < 4; ry++) {
        float4 uA = *(const float4*)(xA + (size_t)(2 * ry) * WW);
        float4 wA = *(const float4*)(xA + (size_t)(2 * ry + 1) * WW);
        float4 uB = *(const float4*)(xB + (size_t)(2 * ry) * WW);
        float4 wB = *(const float4*)(xB + (size_t)(2 * ry + 1) * WW);

        const size_t i = (size_t)(r * 4 + ry) * 512 + 2 * g;   // even
        const float* ph = Wd3 + 3 * i;
        const float* pv = Wd3 + 3 * (N1c + i);
        const float* pd = Wd3 + 3 * (2 * (size_t)N1c + i);
        float2 ha = *(const float2*)(ph), hb = *(const float2*)(ph + 2), hc = *(const float2*)(ph + 4);
        float2 va = *(const float2*)(pv), vb = *(const float2*)(pv + 2), vc = *(const float2*)(pv + 4);
        float2 da = *(const float2*)(pd), db = *(const float2*)(pd + 2), dc = *(const float2*)(pd + 4);

        float h0, v0, d0, h1, v1, d1;
        haar_fwd(uA.x, uA.y, wA.x, wA.y, a0A[ry], h0, v0, d0);
        haar_fwd(uA.z, uA.w, wA.z, wA.w, a1A[ry], h1, v1, d1);
        s1xA += h0 * ha.x + h1 * hb.y + v0 * va.x + v1 * vb.y + d0 * da.x + d1 * db.y;
        s1yA += h0 * ha.y + h1 * hc.x + v0 * va.y + v1 * vc.x + d0 * da.y + d1 * dc.x;
        s1zA += h0 * hb.x + h1 * hc.y + v0 * vb.x + v1 * vc.y + d0 * db.x + d1 * dc.y;

        haar_fwd(uB.x, uB.y, wB.x, wB.y, a0B[ry], h0, v0, d0);
        haar_fwd(uB.z, uB.w, wB.z, wB.w, a1B[ry], h1, v1, d1);
        s1xB += h0 * ha.x + h1 * hb.y + v0 * va.x + v1 * vb.y + d0 * da.x + d1 * db.y;
        s1yB += h0 * ha.y + h1 * hc.x + v0 * va.y + v1 * vc.x + d0 * da.y + d1 * dc.x;
        s1zB += h0 * hb.x + h1 * hc.y + v0 * vb.x + v1 * vc.y + d0 * db.x + d1 * dc.y;
    }

    // ---- level 2 ----
    float a2A[2], a2B[2];
    #pragma unroll
    for (int ry2 = 0; ry2 < 2; ry2++) {
        const size_t i = (size_t)(r * 2 + ry2) * 256 + g;
        const float* ph = Wd2 + 3 * i;
        const float* pv = Wd2 + 3 * (N2c + i);
        const float* pd = Wd2 + 3 * (2 * (size_t)N2c + i);
        float w0 = __ldg(ph + 0), w1 = __ldg(ph + 1), w2 = __ldg(ph + 2);
        float w3 = __ldg(pv + 0), w4 = __ldg(pv + 1), w5 = __ldg(pv + 2);
        float w6 = __ldg(pd + 0), w7 = __ldg(pd + 1), w8 = __ldg(pd + 2);

        float h, v, dd;
        haar_fwd(a0A[2*ry2], a1A[2*ry2], a0A[2*ry2+1], a1A[2*ry2+1], a2A[ry2], h, v, dd);
        s2xA += h * w0 + v * w3 + dd * w6;
        s2yA += h * w1 + v * w4 + dd * w7;
        s2zA += h * w2 + v * w5 + dd * w8;

        haar_fwd(a0B[2*ry2], a1B[2*ry2], a0B[2*ry2+1], a1B[2*ry2+1], a2B[ry2], h, v, dd);
        s2xB += h * w0 + v * w3 + dd * w6;
        s2yB += h * w1 + v * w4 + dd * w7;
        s2zB += h * w2 + v * w5 + dd * w8;
    }

    // ---- level 3: combine lane pairs; only even lane accumulates ----
    {
        float pA0 = __shfl_xor_sync(0xFFFFFFFFu, a2A[0], 1);
        float pA1 = __shfl_xor_sync(0xFFFFFFFFu, a2A[1], 1);
        float pB0 = __shfl_xor_sync(0xFFFFFFFFu, a2B[0], 1);
        float pB1 = __shfl_xor_sync(0xFFFFFFFFu, a2B[1], 1);
        if ((g & 1) == 0) {
            const size_t i = (size_t)r * 128 + (g >> 1);
            const float* ph = Wd1 + 3 * i;
            const float* pv = Wd1 + 3 * (N3c + i);
            const float* pd = Wd1 + 3 * (2 * (size_t)N3c + i);
            float w0 = __ldg(ph + 0), w1 = __ldg(ph + 1), w2 = __ldg(ph + 2);
            float w3 = __ldg(pv + 0), w4 = __ldg(pv + 1), w5 = __ldg(pv + 2);
            float w6 = __ldg(pd + 0), w7 = __ldg(pd + 1), w8 = __ldg(pd + 2);
            float wa = __ldg(Wa + i);

            float a, h, v, dd;
            haar_fwd(a2A[0], pA0, a2A[1], pA1, a, h, v, dd);
            s3xA = h * w0 + v * w3 + dd * w6;
            s3yA = h * w1 + v * w4 + dd * w7;
            s3zA = h * w2 + v * w5 + dd * w8;
            saA  = a * wa;

            haar_fwd(a2B[0], pB0, a2B[1], pB1, a, h, v, dd);
            s3xB = h * w0 + v * w3 + dd * w6;
            s3yB = h * w1 + v * w4 + dd * w7;
            s3zB = h * w2 + v * w5 + dd * w8;
            saB  = a * wa;
        }
    }

    // ---- block reduction of 20 scalars -> per-CTA partials ----
    float vals[20] = {saA, s3xA, s3yA, s3zA, s2xA, s2yA, s2zA, s1xA, s1yA, s1zA,
                      saB, s3xB, s3yB, s3zB, s2xB, s2yB, s2zB, s1xB, s1yB, s1zB};
    __shared__ float sm[20][8];
    int lane = threadIdx.x & 31;
    int wid  = threadIdx.x >> 5;
    #pragma unroll
    for (int k = 0; k < 20; k++) {
        float v = vals[k];
        #pragma unroll
        for (int off2 = 16; off2 > 0; off2 >>= 1)
            v += __shfl_down_sync(0xFFFFFFFFu, v, off2);
        if (lane == 0) sm[k][wid] = v;
    }
    __syncthreads();
    if (threadIdx.x < 20) {
        float t = 0.f;
        #pragma unroll
        for (int w = 0; w < 8; w++) t += sm[threadIdx.x][w];
        g_part[(blockIdx.y * 20 + threadIdx.x) * FWD_BLOCKS + blockIdx.x] = t;
    }
}

// ---------------------------------------------------------------------------
// K2: reduce partials + compute gates. grid = NB blocks x 128 threads.
// ---------------------------------------------------------------------------
__global__ void __launch_bounds__(128) k_gates(
    const float* __restrict__ ba,
    const float* __restrict__ bd1,
    const float* __restrict__ bd2,
    const float* __restrict__ bd3)
{
    const int batch = blockIdx.x;
    const int pair = batch >> 1;
    const int sub  = (batch & 1) * 10;
    const int tid = threadIdx.x;
    const int lane = tid & 31;
    const int wid  = tid >> 5;

    __shared__ float red[10];
    __shared__ float wsum[4];

    #pragma unroll
    for (int k = 0; k < 10; k++) {
        float v = g_part[(pair * 20 + sub + k) * FWD_BLOCKS + tid];
        #pragma unroll
        for (int off = 16; off > 0; off >>= 1)
            v += __shfl_down_sync(0xFFFFFFFFu, v, off);
        if (lane == 0) wsum[wid] = v;
        __syncthreads();
        if (tid == 0) red[k] = wsum[0] + wsum[1] + wsum[2] + wsum[3];
        __syncthreads();
    }

    if (tid == 0) {
        float* G = g_gates + batch * 10;
        G[0] = 1.0f / (1.0f + __expf(-(red[0] + ba[0])));
        const float* bds[3] = {bd1, bd2, bd3};
        #pragma unroll
        for (int s = 0; s < 3; s++) {
            float l0 = red[1 + 3*s] + bds[s][0];
            float l1 = red[2 + 3*s] + bds[s][1];
            float l2 = red[3 + 3*s] + bds[s][2];
            float m = fmaxf(fmaxf(l0, l1), l2);
            float e0 = __expf(l0 - m), e1 = __expf(l1 - m), e2 = __expf(l2 - m);
            float inv = 1.0f / (e0 + e1 + e2);
            G[1 + 3*s] = e0 * inv; G[2 + 3*s] = e1 * inv; G[3 + 3*s] = e2 * inv;
        }
    }
}

// ---------------------------------------------------------------------------
// K3: single-pass reconstruct (4 cols x 8 rows, float4 I/O).
// Level-3 computed symmetrically in both lanes of a pair (shfl_xor 1).
// grid: (128, NB) x 256.
// ---------------------------------------------------------------------------
__global__ void __launch_bounds__(256) k_recon(
    const float* __restrict__ x, float* __restrict__ out)
{
    const int batch = blockIdx.y;
    const int bt = blockIdx.x * blockDim.x + threadIdx.x;
    const int g = bt & 255;
    const int r = bt >> 8;
    const size_t base = (size_t)batch * (HH * WW) + (size_t)(r * 8) * WW + g * 4;
    const float* xb = x + base;
    float* ob = out + base;

    const float* G = g_gates + batch * 10;
    const float aw  = __ldg(G + 0);
    const float g3h = __ldg(G + 1), g3v = __ldg(G + 2), g3d = __ldg(G + 3);
    const float g2h = __ldg(G + 4), g2v = __ldg(G + 5), g2d = __ldg(G + 6);
    const float g1h = __ldg(G + 7), g1v = __ldg(G + 8), g1d = __ldg(G + 9);

    // ---- forward level 1 (store gated details) ----
    float a1_0[4], a1_1[4];
    float h1_0[4], v1_0[4], d1_0[4];
    float h1_1[4], v1_1[4], d1_1[4];
    #pragma unroll
    for (int ry = 0; ry < 4; ry++) {
        float4 u = *(const float4*)(xb + (size_t)(2 * ry) * WW);
        float4 w = *(const float4*)(xb + (size_t)(2 * ry + 1) * WW);
        float h, v, dd;
        haar_fwd(u.x, u.y, w.x, w.y, a1_0[ry], h, v, dd);
        h1_0[ry] = h * g1h; v1_0[ry] = v * g1v; d1_0[ry] = dd * g1d;
        haar_fwd(u.z, u.w, w.z, w.w, a1_1[ry], h, v, dd);
        h1_1[ry] = h * g1h; v1_1[ry] = v * g1v; d1_1[ry] = dd * g1d;
    }

    // ---- forward level 2 (gated) ----
    float a2[2], h2[2], v2[2], d2[2];
    #pragma unroll
    for (int ry2 = 0; ry2 < 2; ry2++) {
        float h, v, dd;
        haar_fwd(a1_0[2*ry2], a1_1[2*ry2], a1_0[2*ry2+1], a1_1[2*ry2+1],
                 a2[ry2], h, v, dd);
        h2[ry2] = h * g2h; v2[ry2] = v * g2v; d2[ry2] = dd * g2d;
    }

    // ---- level 3: symmetric in both lanes of the pair ----
    float R2[2];
    {
        float pa0 = __shfl_xor_sync(0xFFFFFFFFu, a2[0], 1);
        float pa1 = __shfl_xor_sync(0xFFFFFFFFu, a2[1], 1);
        bool odd = (g & 1);
        float lo0 = odd ? pa0 : a2[0], hi0 = odd ? a2[0] : pa0;
        float lo1 = odd ? pa1 : a2[1], hi1 = odd ? a2[1] : pa1;
        float a, h, v, dd;
        haar_fwd(lo0, hi0, lo1, hi1, a, h, v, dd);
        a *= aw; h *= g3h; v *= g3v; dd *= g3d;
        float x00, x01, x10, x11;
        haar_inv(a, h, v, dd, x00, x01, x10, x11);
        R2[0] = odd ? x01 : x00;
        R2[1] = odd ? x11 : x10;
    }

    // ---- inverse level 2 ----
    float r1_0[4], r1_1[4];
    #pragma unroll
    for (int ry2 = 0; ry2 < 2; ry2++) {
        haar_inv(R2[ry2], h2[ry2], v2[ry2], d2[ry2],
                 r1_0[2*ry2], r1_1[2*ry2], r1_0[2*ry2+1], r1_1[2*ry2+1]);
    }

    // ---- inverse level 1 + coalesced float4 stores ----
    #pragma unroll
    for (int ry = 0; ry < 4; ry++) {
        float p00, p01, p10, p11, q00, q01, q10, q11;
        haar_inv(r1_0[ry], h1_0[ry], v1_0[ry], d1_0[ry], p00, p01, p10, p11);
        haar_inv(r1_1[ry], h1_1[ry], v1_1[ry], d1_1[ry], q00, q01, q10, q11);
        *(float4*)(ob + (size_t)(2 * ry) * WW)     = make_float4(p00, p01, q00, q01);
        *(float4*)(ob + (size_t)(2 * ry + 1) * WW) = make_float4(p10, p11, q10, q11);
    }
}

// ---------------------------------------------------------------------------
extern "C" void kernel_launch(void* const* d_in, const int* in_sizes, int n_in,
                              void* d_out, int out_size) {
    const float* x   = (const float*)d_in[0];
    const float* Wa  = (const float*)d_in[1];
    const float* ba  = (const float*)d_in[2];
    const float* Wd1 = (const float*)d_in[3];
    const float* bd1 = (const float*)d_in[4];
    const float* Wd2 = (const float*)d_in[5];
    const float* bd2 = (const float*)d_in[6];
    const float* Wd3 = (const float*)d_in[7];
    const float* bd3 = (const float*)d_in[8];
    float* out = (float*)d_out;

    k_forward<<<dim3(FWD_BLOCKS, NB / 2), 256>>>(x, Wa, Wd1, Wd2, Wd3);
    k_gates<<<NB, 128>>>(ba, bd1, bd2, bd3);
    k_recon<<<dim3(128, NB), 256>>>(x, out);
}

// round 8
// speedup vs baseline: 1.1559x; 1.0103x over previous
#include <cuda_runtime.h>

// WaveletAttention: 3-level Haar DWT -> per-batch scalar gates -> gated IDWT.
// R8: (a) k_gates kernel deleted; gate reduction fused into k_recon (forward
//     transform is gate-independent, so the reduction overlaps it; one
//     barrier, gates computed redundantly per thread). (b) k_forward
//     __launch_bounds__(256,5) to buy a 5th CTA/SM (was 62 regs -> 4 CTAs).

#define HH 1024
#define WW 1024
#define NB 16
#define N1c 262144   // 512*512 per component, weights Wd3 (finest)
#define N2c 65536    // 256*256, weights Wd2
#define N3c 16384    // 128*128, weights Wd1 (coarsest)
#define FWD_BLOCKS 128   // gridDim.x of k_forward

// partials: [pair][20][FWD_BLOCKS]
// per-batch 10 logits: [0] approx, [1:4] L3 (Wd1), [4:7] L2 (Wd2), [7:10] L1 (Wd3)
__device__ float g_part[(NB / 2) * 20 * FWD_BLOCKS];

__device__ __forceinline__ void haar_fwd(float x00, float x01, float x10, float x11,
                                         float& a, float& h, float& v, float& dd) {
    float s0 = x00 + x01, m0 = x00 - x01;
    float s1 = x10 + x11, m1 = x10 - x11;
    a  = 0.5f * (s0 + s1);
    h  = 0.5f * (s0 - s1);
    v  = 0.5f * (m0 + m1);
    dd = 0.5f * (m0 - m1);
}

__device__ __forceinline__ void haar_inv(float a, float h, float v, float dd,
                                         float& x00, float& x01, float& x10, float& x11) {
    float ph = a + h, mh = a - h;
    float pv = v + dd, mv = v - dd;
    x00 = 0.5f * (ph + pv);
    x01 = 0.5f * (ph - pv);
    x10 = 0.5f * (mh + mv);
    x11 = 0.5f * (mh - mv);
}

// ---------------------------------------------------------------------------
// K1: forward DWT + logit partials, TWO batches per thread.
// Thread = col-group g (4 cols) x 8 rows. grid: (FWD_BLOCKS, NB/2) x 256.
// ---------------------------------------------------------------------------
__global__ void __launch_bounds__(256, 5) k_forward(
    const float* __restrict__ x,
    const float* __restrict__ Wa,
    const float* __restrict__ Wd1,   // [3*N3c, 3] coarsest
    const float* __restrict__ Wd2,   // [3*N2c, 3]
    const float* __restrict__ Wd3)   // [3*N1c, 3] finest
{
    const int b0 = blockIdx.y * 2;
    const int bt = blockIdx.x * blockDim.x + threadIdx.x;   // 0..32767
    const int g = bt & 255;
    const int r = bt >> 8;
    const size_t off = (size_t)(r * 8) * WW + g * 4;
    const float* xA = x + (size_t)b0 * (HH * WW) + off;
    const float* xB = xA + (size_t)(HH * WW);

    float saA = 0.f, s1xA = 0.f, s1yA = 0.f, s1zA = 0.f;
    float s2xA = 0.f, s2yA = 0.f, s2zA = 0.f, s3xA = 0.f, s3yA = 0.f, s3zA = 0.f;
    float saB = 0.f, s1xB = 0.f, s1yB = 0.f, s1zB = 0.f;
    float s2xB = 0.f, s2yB = 0.f, s2zB = 0.f, s3xB = 0.f, s3yB = 0.f, s3zB = 0.f;

    float a0A[4], a1A[4], a0B[4], a1B[4];

    // ---- level 1 ----
    #pragma unroll
    for (int ry = 0; ry < 4; ry++) {
        float4 uA = *(const float4*)(xA + (size_t)(2 * ry) * WW);
        float4 wA = *(const float4*)(xA + (size_t)(2 * ry + 1) * WW);
        float4 uB = *(const float4*)(xB + (size_t)(2 * ry) * WW);
        float4 wB = *(const float4*)(xB + (size_t)(2 * ry + 1) * WW);

        const size_t i = (size_t)(r * 4 + ry) * 512 + 2 * g;   // even
        const float* ph = Wd3 + 3 * i;
        const float* pv = Wd3 + 3 * (N1c + i);
        const float* pd = Wd3 + 3 * (2 * (size_t)N1c + i);
        float2 ha = *(const float2*)(ph), hb = *(const float2*)(ph + 2), hc = *(const float2*)(ph + 4);
        float2 va = *(const float2*)(pv), vb = *(const float2*)(pv + 2), vc = *(const float2*)(pv + 4);
        float2 da = *(const float2*)(pd), db = *(const float2*)(pd + 2), dc = *(const float2*)(pd + 4);

        float h0, v0, d0, h1, v1, d1;
        haar_fwd(uA.x, uA.y, wA.x, wA.y, a0A[ry], h0, v0, d0);
        haar_fwd(uA.z, uA.w, wA.z, wA.w, a1A[ry], h1, v1, d1);
        s1xA += h0 * ha.x + h1 * hb.y + v0 * va.x + v1 * vb.y + d0 * da.x + d1 * db.y;
        s1yA += h0 * ha.y + h1 * hc.x + v0 * va.y + v1 * vc.x + d0 * da.y + d1 * dc.x;
        s1zA += h0 * hb.x + h1 * hc.y + v0 * vb.x + v1 * vc.y + d0 * db.x + d1 * dc.y;

        haar_fwd(uB.x, uB.y, wB.x, wB.y, a0B[ry], h0, v0, d0);
        haar_fwd(uB.z, uB.w, wB.z, wB.w, a1B[ry], h1, v1, d1);
        s1xB += h0 * ha.x + h1 * hb.y + v0 * va.x + v1 * vb.y + d0 * da.x + d1 * db.y;
        s1yB += h0 * ha.y + h1 * hc.x + v0 * va.y + v1 * vc.x + d0 * da.y + d1 * dc.x;
        s1zB += h0 * hb.x + h1 * hc.y + v0 * vb.x + v1 * vc.y + d0 * db.x + d1 * dc.y;
    }

    // ---- level 2 ----
    float a2A[2], a2B[2];
    #pragma unroll
    for (int ry2 = 0; ry2 < 2; ry2++) {
        const size_t i = (size_t)(r * 2 + ry2) * 256 + g;
        const float* ph = Wd2 + 3 * i;
        const float* pv = Wd2 + 3 * (N2c + i);
        const float* pd = Wd2 + 3 * (2 * (size_t)N2c + i);
        float w0 = __ldg(ph + 0), w1 = __ldg(ph + 1), w2 = __ldg(ph + 2);
        float w3 = __ldg(pv + 0), w4 = __ldg(pv + 1), w5 = __ldg(pv + 2);
        float w6 = __ldg(pd + 0), w7 = __ldg(pd + 1), w8 = __ldg(pd + 2);

        float h, v, dd;
        haar_fwd(a0A[2*ry2], a1A[2*ry2], a0A[2*ry2+1], a1A[2*ry2+1], a2A[ry2], h, v, dd);
        s2xA += h * w0 + v * w3 + dd * w6;
        s2yA += h * w1 + v * w4 + dd * w7;
        s2zA += h * w2 + v * w5 + dd * w8;

        haar_fwd(a0B[2*ry2], a1B[2*ry2], a0B[2*ry2+1], a1B[2*ry2+1], a2B[ry2], h, v, dd);
        s2xB += h * w0 + v * w3 + dd * w6;
        s2yB += h * w1 + v * w4 + dd * w7;
        s2zB += h * w2 + v * w5 + dd * w8;
    }

    // ---- level 3: combine lane pairs; only even lane accumulates ----
    {
        float pA0 = __shfl_xor_sync(0xFFFFFFFFu, a2A[0], 1);
        float pA1 = __shfl_xor_sync(0xFFFFFFFFu, a2A[1], 1);
        float pB0 = __shfl_xor_sync(0xFFFFFFFFu, a2B[0], 1);
        float pB1 = __shfl_xor_sync(0xFFFFFFFFu, a2B[1], 1);
        if ((g & 1) == 0) {
            const size_t i = (size_t)r * 128 + (g >> 1);
            const float* ph = Wd1 + 3 * i;
            const float* pv = Wd1 + 3 * (N3c + i);
            const float* pd = Wd1 + 3 * (2 * (size_t)N3c + i);
            float w0 = __ldg(ph + 0), w1 = __ldg(ph + 1), w2 = __ldg(ph + 2);
            float w3 = __ldg(pv + 0), w4 = __ldg(pv + 1), w5 = __ldg(pv + 2);
            float w6 = __ldg(pd + 0), w7 = __ldg(pd + 1), w8 = __ldg(pd + 2);
            float wa = __ldg(Wa + i);

            float a, h, v, dd;
            haar_fwd(a2A[0], pA0, a2A[1], pA1, a, h, v, dd);
            s3xA = h * w0 + v * w3 + dd * w6;
            s3yA = h * w1 + v * w4 + dd * w7;
            s3zA = h * w2 + v * w5 + dd * w8;
            saA  = a * wa;

            haar_fwd(a2B[0], pB0, a2B[1], pB1, a, h, v, dd);
            s3xB = h * w0 + v * w3 + dd * w6;
            s3yB = h * w1 + v * w4 + dd * w7;
            s3zB = h * w2 + v * w5 + dd * w8;
            saB  = a * wa;
        }
    }

    // ---- block reduction of 20 scalars -> per-CTA partials ----
    float vals[20] = {saA, s3xA, s3yA, s3zA, s2xA, s2yA, s2zA, s1xA, s1yA, s1zA,
                      saB, s3xB, s3yB, s3zB, s2xB, s2yB, s2zB, s1xB, s1yB, s1zB};
    __shared__ float sm[20][8];
    int lane = threadIdx.x & 31;
    int wid  = threadIdx.x >> 5;
    #pragma unroll
    for (int k = 0; k < 20; k++) {
        float v = vals[k];
        #pragma unroll
        for (int off2 = 16; off2 > 0; off2 >>= 1)
            v += __shfl_down_sync(0xFFFFFFFFu, v, off2);
        if (lane == 0) sm[k][wid] = v;
    }
    __syncthreads();
    if (threadIdx.x < 20) {
        float t = 0.f;
        #pragma unroll
        for (int w = 0; w < 8; w++) t += sm[threadIdx.x][w];
        g_part[(blockIdx.y * 20 + threadIdx.x) * FWD_BLOCKS + blockIdx.x] = t;
    }
}

// ---------------------------------------------------------------------------
// K2: reconstruct with FUSED gate reduction.
// Forward transform (gate-independent) computed first; one warp-parallel
// reduction of this batch's 10x128 partials (single barrier); every thread
// computes the 10 gates redundantly; then gate + inverse + store.
// grid: (128, NB) x 256.
// ---------------------------------------------------------------------------
__global__ void __launch_bounds__(256) k_recon(
    const float* __restrict__ x, float* __restrict__ out,
    const float* __restrict__ ba,
    const float* __restrict__ bd1,
    const float* __restrict__ bd2,
    const float* __restrict__ bd3)
{
    const int batch = blockIdx.y;
    const int bt = blockIdx.x * blockDim.x + threadIdx.x;
    const int g = bt & 255;
    const int r = bt >> 8;
    const size_t base = (size_t)batch * (HH * WW) + (size_t)(r * 8) * WW + g * 4;
    const float* xb = x + base;
    float* ob = out + base;

    // ---- forward level 1 (UNGATED) ----
    float a1_0[4], a1_1[4];
    float h1_0[4], v1_0[4], d1_0[4];
    float h1_1[4], v1_1[4], d1_1[4];
    #pragma unroll
    for (int ry = 0; ry < 4; ry++) {
        float4 u = *(const float4*)(xb + (size_t)(2 * ry) * WW);
        float4 w = *(const float4*)(xb + (size_t)(2 * ry + 1) * WW);
        haar_fwd(u.x, u.y, w.x, w.y, a1_0[ry], h1_0[ry], v1_0[ry], d1_0[ry]);
        haar_fwd(u.z, u.w, w.z, w.w, a1_1[ry], h1_1[ry], v1_1[ry], d1_1[ry]);
    }

    // ---- forward level 2 (UNGATED) ----
    float a2[2], h2[2], v2[2], d2[2];
    #pragma unroll
    for (int ry2 = 0; ry2 < 2; ry2++) {
        haar_fwd(a1_0[2*ry2], a1_1[2*ry2], a1_0[2*ry2+1], a1_1[2*ry2+1],
                 a2[ry2], h2[ry2], v2[ry2], d2[ry2]);
    }

    // ---- forward level 3 (UNGATED, symmetric in lane pair) ----
    const bool odd = (g & 1);
    float a3, h3, v3, d3;
    {
        float pa0 = __shfl_xor_sync(0xFFFFFFFFu, a2[0], 1);
        float pa1 = __shfl_xor_sync(0xFFFFFFFFu, a2[1], 1);
        float lo0 = odd ? pa0 : a2[0], hi0 = odd ? a2[0] : pa0;
        float lo1 = odd ? pa1 : a2[1], hi1 = odd ? a2[1] : pa1;
        haar_fwd(lo0, hi0, lo1, hi1, a3, h3, v3, d3);
    }

    // ---- fused gate reduction: 10 logits from 128 partials each ----
    __shared__ float red[10];
    {
        const int lane = threadIdx.x & 31;
        const int wid  = threadIdx.x >> 5;
        const int pbase = (batch >> 1) * 20 + (batch & 1) * 10;
        for (int k = wid; k < 10; k += 8) {
            const float* p = g_part + (size_t)(pbase + k) * FWD_BLOCKS;
            float v = p[lane] + p[lane + 32] + p[lane + 64] + p[lane + 96];
            #pragma unroll
            for (int off = 16; off > 0; off >>= 1)
                v += __shfl_down_sync(0xFFFFFFFFu, v, off);
            if (lane == 0) red[k] = v;
        }
    }
    __syncthreads();

    // ---- per-thread gate computation (deterministic, identical per block) ----
    float aw = 1.0f / (1.0f + __expf(-(red[0] + ba[0])));
    float g3h, g3v, g3d, g2h, g2v, g2d, g1h, g1v, g1d;
    {
        float l0 = red[1] + bd1[0], l1 = red[2] + bd1[1], l2 = red[3] + bd1[2];
        float m = fmaxf(fmaxf(l0, l1), l2);
        float e0 = __expf(l0 - m), e1 = __expf(l1 - m), e2 = __expf(l2 - m);
        float inv = 1.0f / (e0 + e1 + e2);
        g3h = e0 * inv; g3v = e1 * inv; g3d = e2 * inv;
    }
    {
        float l0 = red[4] + bd2[0], l1 = red[5] + bd2[1], l2 = red[6] + bd2[2];
        float m = fmaxf(fmaxf(l0, l1), l2);
        float e0 = __expf(l0 - m), e1 = __expf(l1 - m), e2 = __expf(l2 - m);
        float inv = 1.0f / (e0 + e1 + e2);
        g2h = e0 * inv; g2v = e1 * inv; g2d = e2 * inv;
    }
    {
        float l0 = red[7] + bd3[0], l1 = red[8] + bd3[1], l2 = red[9] + bd3[2];
        float m = fmaxf(fmaxf(l0, l1), l2);
        float e0 = __expf(l0 - m), e1 = __expf(l1 - m), e2 = __expf(l2 - m);
        float inv = 1.0f / (e0 + e1 + e2);
        g1h = e0 * inv; g1v = e1 * inv; g1d = e2 * inv;
    }

    // ---- gate L3, invert L3 ----
    float R2[2];
    {
        float a = a3 * aw, h = h3 * g3h, v = v3 * g3v, dd = d3 * g3d;
        float x00, x01, x10, x11;
        haar_inv(a, h, v, dd, x00, x01, x10, x11);
        R2[0] = odd ? x01 : x00;
        R2[1] = odd ? x11 : x10;
    }

    // ---- inverse level 2 (gated) ----
    float r1_0[4], r1_1[4];
    #pragma unroll
    for (int ry2 = 0; ry2 < 2; ry2++) {
        haar_inv(R2[ry2], h2[ry2] * g2h, v2[ry2] * g2v, d2[ry2] * g2d,
                 r1_0[2*ry2], r1_1[2*ry2], r1_0[2*ry2+1], r1_1[2*ry2+1]);
    }

    // ---- inverse level 1 (gated) + coalesced float4 stores ----
    #pragma unroll
    for (int ry = 0; ry < 4; ry++) {
        float p00, p01, p10, p11, q00, q01, q10, q11;
        haar_inv(r1_0[ry], h1_0[ry] * g1h, v1_0[ry] * g1v, d1_0[ry] * g1d,
                 p00, p01, p10, p11);
        haar_inv(r1_1[ry], h1_1[ry] * g1h, v1_1[ry] * g1v, d1_1[ry] * g1d,
                 q00, q01, q10, q11);
        *(float4*)(ob + (size_t)(2 * ry) * WW)     = make_float4(p00, p01, q00, q01);
        *(float4*)(ob + (size_t)(2 * ry + 1) * WW) = make_float4(p10, p11, q10, q11);
    }
}

// ---------------------------------------------------------------------------
extern "C" void kernel_launch(void* const* d_in, const int* in_sizes, int n_in,
                              void* d_out, int out_size) {
    const float* x   = (const float*)d_in[0];
    const float* Wa  = (const float*)d_in[1];
    const float* ba  = (const float*)d_in[2];
    const float* Wd1 = (const float*)d_in[3];
    const float* bd1 = (const float*)d_in[4];
    const float* Wd2 = (const float*)d_in[5];
    const float* bd2 = (const float*)d_in[6];
    const float* Wd3 = (const float*)d_in[7];
    const float* bd3 = (const float*)d_in[8];
    float* out = (float*)d_out;

    k_forward<<<dim3(FWD_BLOCKS, NB / 2), 256>>>(x, Wa, Wd1, Wd2, Wd3);
    k_recon<<<dim3(128, NB), 256>>>(x, out, ba, bd1, bd2, bd3);
}

// round 9
// speedup vs baseline: 1.2000x; 1.0381x over previous
#include <cuda_runtime.h>

// WaveletAttention: 3-level Haar DWT -> per-batch scalar gates -> gated IDWT.
// R9: two launches only.
//   k_forward (R7 body, 22.4us measured) + last-CTA-per-pair gate
//   finalization (threadfence + atomicInc wrap counter; deterministic,
//   graph-replay safe). k_recon = exact R3/R4 proven kernel (20.4us).

#define HH 1024
#define WW 1024
#define NB 16
#define N1c 262144   // 512*512 per component, weights Wd3 (finest)
#define N2c 65536    // 256*256, weights Wd2
#define N3c 16384    // 128*128, weights Wd1 (coarsest)
#define FWD_BLOCKS 128   // gridDim.x of k_forward

// partials: [pair][20][FWD_BLOCKS]
// gates per batch (10): [0] approx sigmoid, [1:4] L3, [4:7] L2, [7:10] L1
__device__ float g_part[(NB / 2) * 20 * FWD_BLOCKS];
__device__ float g_gates[NB * 10];
__device__ unsigned int g_cnt[NB / 2];   // zero-initialized; wraps back to 0

__device__ __forceinline__ void haar_fwd(float x00, float x01, float x10, float x11,
                                         float& a, float& h, float& v, float& dd) {
    float s0 = x00 + x01, m0 = x00 - x01;
    float s1 = x10 + x11, m1 = x10 - x11;
    a  = 0.5f * (s0 + s1);
    h  = 0.5f * (s0 - s1);
    v  = 0.5f * (m0 + m1);
    dd = 0.5f * (m0 - m1);
}

__device__ __forceinline__ void haar_inv(float a, float h, float v, float dd,
                                         float& x00, float& x01, float& x10, float& x11) {
    float ph = a + h, mh = a - h;
    float pv = v + dd, mv = v - dd;
    x00 = 0.5f * (ph + pv);
    x01 = 0.5f * (ph - pv);
    x10 = 0.5f * (mh + mv);
    x11 = 0.5f * (mh - mv);
}

__device__ __forceinline__ void softmax3g(float l0, float l1, float l2, float* out) {
    float m = fmaxf(fmaxf(l0, l1), l2);
    float e0 = __expf(l0 - m), e1 = __expf(l1 - m), e2 = __expf(l2 - m);
    float inv = 1.0f / (e0 + e1 + e2);
    out[0] = e0 * inv; out[1] = e1 * inv; out[2] = e2 * inv;
}

// ---------------------------------------------------------------------------
// K1: forward DWT + logit partials, TWO batches per thread; the last CTA of
// each batch-pair reduces partials and writes the gates.
// grid: (FWD_BLOCKS, NB/2) x 256.
// ---------------------------------------------------------------------------
__global__ void __launch_bounds__(256) k_forward(
    const float* __restrict__ x,
    const float* __restrict__ Wa,
    const float* __restrict__ Wd1,   // [3*N3c, 3] coarsest
    const float* __restrict__ Wd2,   // [3*N2c, 3]
    const float* __restrict__ Wd3,   // [3*N1c, 3] finest
    const float* __restrict__ ba,
    const float* __restrict__ bd1,
    const float* __restrict__ bd2,
    const float* __restrict__ bd3)
{
    const int b0 = blockIdx.y * 2;
    const int bt = blockIdx.x * blockDim.x + threadIdx.x;   // 0..32767
    const int g = bt & 255;
    const int r = bt >> 8;
    const size_t off = (size_t)(r * 8) * WW + g * 4;
    const float* xA = x + (size_t)b0 * (HH * WW) + off;
    const float* xB = xA + (size_t)(HH * WW);

    float saA = 0.f, s1xA = 0.f, s1yA = 0.f, s1zA = 0.f;
    float s2xA = 0.f, s2yA = 0.f, s2zA = 0.f, s3xA = 0.f, s3yA = 0.f, s3zA = 0.f;
    float saB = 0.f, s1xB = 0.f, s1yB = 0.f, s1zB = 0.f;
    float s2xB = 0.f, s2yB = 0.f, s2zB = 0.f, s3xB = 0.f, s3yB = 0.f, s3zB = 0.f;

    float a0A[4], a1A[4], a0B[4], a1B[4];

    // ---- level 1 ----
    #pragma unroll
    for (int ry = 0; ry < 4; ry++) {
        float4 uA = *(const float4*)(xA + (size_t)(2 * ry) * WW);
        float4 wA = *(const float4*)(xA + (size_t)(2 * ry + 1) * WW);
        float4 uB = *(const float4*)(xB + (size_t)(2 * ry) * WW);
        float4 wB = *(const float4*)(xB + (size_t)(2 * ry + 1) * WW);

        const size_t i = (size_t)(r * 4 + ry) * 512 + 2 * g;   // even
        const float* ph = Wd3 + 3 * i;
        const float* pv = Wd3 + 3 * (N1c + i);
        const float* pd = Wd3 + 3 * (2 * (size_t)N1c + i);
        float2 ha = *(const float2*)(ph), hb = *(const float2*)(ph + 2), hc = *(const float2*)(ph + 4);
        float2 va = *(const float2*)(pv), vb = *(const float2*)(pv + 2), vc = *(const float2*)(pv + 4);
        float2 da = *(const float2*)(pd), db = *(const float2*)(pd + 2), dc = *(const float2*)(pd + 4);

        float h0, v0, d0, h1, v1, d1;
        haar_fwd(uA.x, uA.y, wA.x, wA.y, a0A[ry], h0, v0, d0);
        haar_fwd(uA.z, uA.w, wA.z, wA.w, a1A[ry], h1, v1, d1);
        s1xA += h0 * ha.x + h1 * hb.y + v0 * va.x + v1 * vb.y + d0 * da.x + d1 * db.y;
        s1yA += h0 * ha.y + h1 * hc.x + v0 * va.y + v1 * vc.x + d0 * da.y + d1 * dc.x;
        s1zA += h0 * hb.x + h1 * hc.y + v0 * vb.x + v1 * vc.y + d0 * db.x + d1 * dc.y;

        haar_fwd(uB.x, uB.y, wB.x, wB.y, a0B[ry], h0, v0, d0);
        haar_fwd(uB.z, uB.w, wB.z, wB.w, a1B[ry], h1, v1, d1);
        s1xB += h0 * ha.x + h1 * hb.y + v0 * va.x + v1 * vb.y + d0 * da.x + d1 * db.y;
        s1yB += h0 * ha.y + h1 * hc.x + v0 * va.y + v1 * vc.x + d0 * da.y + d1 * dc.x;
        s1zB += h0 * hb.x + h1 * hc.y + v0 * vb.x + v1 * vc.y + d0 * db.x + d1 * dc.y;
    }

    // ---- level 2 ----
    float a2A[2], a2B[2];
    #pragma unroll
    for (int ry2 = 0; ry2 < 2; ry2++) {
        const size_t i = (size_t)(r * 2 + ry2) * 256 + g;
        const float* ph = Wd2 + 3 * i;
        const float* pv = Wd2 + 3 * (N2c + i);
        const float* pd = Wd2 + 3 * (2 * (size_t)N2c + i);
        float w0 = __ldg(ph + 0), w1 = __ldg(ph + 1), w2 = __ldg(ph + 2);
        float w3 = __ldg(pv + 0), w4 = __ldg(pv + 1), w5 = __ldg(pv + 2);
        float w6 = __ldg(pd + 0), w7 = __ldg(pd + 1), w8 = __ldg(pd + 2);

        float h, v, dd;
        haar_fwd(a0A[2*ry2], a1A[2*ry2], a0A[2*ry2+1], a1A[2*ry2+1], a2A[ry2], h, v, dd);
        s2xA += h * w0 + v * w3 + dd * w6;
        s2yA += h * w1 + v * w4 + dd * w7;
        s2zA += h * w2 + v * w5 + dd * w8;

        haar_fwd(a0B[2*ry2], a1B[2*ry2], a0B[2*ry2+1], a1B[2*ry2+1], a2B[ry2], h, v, dd);
        s2xB += h * w0 + v * w3 + dd * w6;
        s2yB += h * w1 + v * w4 + dd * w7;
        s2zB += h * w2 + v * w5 + dd * w8;
    }

    // ---- level 3: combine lane pairs; only even lane accumulates ----
    {
        float pA0 = __shfl_xor_sync(0xFFFFFFFFu, a2A[0], 1);
        float pA1 = __shfl_xor_sync(0xFFFFFFFFu, a2A[1], 1);
        float pB0 = __shfl_xor_sync(0xFFFFFFFFu, a2B[0], 1);
        float pB1 = __shfl_xor_sync(0xFFFFFFFFu, a2B[1], 1);
        if ((g & 1) == 0) {
            const size_t i = (size_t)r * 128 + (g >> 1);
            const float* ph = Wd1 + 3 * i;
            const float* pv = Wd1 + 3 * (N3c + i);
            const float* pd = Wd1 + 3 * (2 * (size_t)N3c + i);
            float w0 = __ldg(ph + 0), w1 = __ldg(ph + 1), w2 = __ldg(ph + 2);
            float w3 = __ldg(pv + 0), w4 = __ldg(pv + 1), w5 = __ldg(pv + 2);
            float w6 = __ldg(pd + 0), w7 = __ldg(pd + 1), w8 = __ldg(pd + 2);
            float wa = __ldg(Wa + i);

            float a, h, v, dd;
            haar_fwd(a2A[0], pA0, a2A[1], pA1, a, h, v, dd);
            s3xA = h * w0 + v * w3 + dd * w6;
            s3yA = h * w1 + v * w4 + dd * w7;
            s3zA = h * w2 + v * w5 + dd * w8;
            saA  = a * wa;

            haar_fwd(a2B[0], pB0, a2B[1], pB1, a, h, v, dd);
            s3xB = h * w0 + v * w3 + dd * w6;
            s3yB = h * w1 + v * w4 + dd * w7;
            s3zB = h * w2 + v * w5 + dd * w8;
            saB  = a * wa;
        }
    }

    // ---- block reduction of 20 scalars -> per-CTA partials ----
    float vals[20] = {saA, s3xA, s3yA, s3zA, s2xA, s2yA, s2zA, s1xA, s1yA, s1zA,
                      saB, s3xB, s3yB, s3zB, s2xB, s2yB, s2zB, s1xB, s1yB, s1zB};
    __shared__ float sm[20][8];
    int lane = threadIdx.x & 31;
    int wid  = threadIdx.x >> 5;
    #pragma unroll
    for (int k = 0; k < 20; k++) {
        float v = vals[k];
        #pragma unroll
        for (int off2 = 16; off2 > 0; off2 >>= 1)
            v += __shfl_down_sync(0xFFFFFFFFu, v, off2);
        if (lane == 0) sm[k][wid] = v;
    }
    __syncthreads();
    if (threadIdx.x < 20) {
        float t = 0.f;
        #pragma unroll
        for (int w = 0; w < 8; w++) t += sm[threadIdx.x][w];
        g_part[(blockIdx.y * 20 + threadIdx.x) * FWD_BLOCKS + blockIdx.x] = t;
    }

    // ---- last CTA of this pair reduces partials and writes gates ----
    __shared__ bool isLast;
    __syncthreads();          // partial stores issued by threads 0..19
    __threadfence();          // make them visible GPU-wide
    if (threadIdx.x == 0) {
        unsigned int old = atomicInc(&g_cnt[blockIdx.y], FWD_BLOCKS - 1);
        isLast = (old == FWD_BLOCKS - 1);   // counter wraps back to 0
    }
    __syncthreads();
    if (!isLast) return;

    __shared__ float red[20];
    for (int k = wid; k < 20; k += 8) {
        const float* p = g_part + (size_t)(blockIdx.y * 20 + k) * FWD_BLOCKS;
        float v = p[lane] + p[lane + 32] + p[lane + 64] + p[lane + 96];
        #pragma unroll
        for (int off2 = 16; off2 > 0; off2 >>= 1)
            v += __shfl_down_sync(0xFFFFFFFFu, v, off2);
        if (lane == 0) red[k] = v;
    }
    __syncthreads();
    if (threadIdx.x < 2) {
        const float* L = red + threadIdx.x * 10;
        float* G = g_gates + (b0 + threadIdx.x) * 10;
        G[0] = 1.0f / (1.0f + __expf(-(L[0] + ba[0])));
        softmax3g(L[1] + bd1[0], L[2] + bd1[1], L[3] + bd1[2], G + 1);
        softmax3g(L[4] + bd2[0], L[5] + bd2[1], L[6] + bd2[2], G + 4);
        softmax3g(L[7] + bd3[0], L[8] + bd3[1], L[9] + bd3[2], G + 7);
    }
}

// ---------------------------------------------------------------------------
// K2: single-pass reconstruct (4 cols x 8 rows, float4 I/O) - proven 20.4us.
// grid: (128, NB) x 256.
// ---------------------------------------------------------------------------
__global__ void __launch_bounds__(256) k_recon(
    const float* __restrict__ x, float* __restrict__ out)
{
    const int batch = blockIdx.y;
    const int bt = blockIdx.x * blockDim.x + threadIdx.x;
    const int g = bt & 255;
    const int r = bt >> 8;
    const size_t base = (size_t)batch * (HH * WW) + (size_t)(r * 8) * WW + g * 4;
    const float* xb = x + base;
    float* ob = out + base;

    const float* G = g_gates + batch * 10;
    const float aw  = __ldg(G + 0);
    const float g3h = __ldg(G + 1), g3v = __ldg(G + 2), g3d = __ldg(G + 3);
    const float g2h = __ldg(G + 4), g2v = __ldg(G + 5), g2d = __ldg(G + 6);
    const float g1h = __ldg(G + 7), g1v = __ldg(G + 8), g1d = __ldg(G + 9);

    // ---- forward level 1 (store gated details) ----
    float a1_0[4], a1_1[4];
    float h1_0[4], v1_0[4], d1_0[4];
    float h1_1[4], v1_1[4], d1_1[4];
    #pragma unroll
    for (int ry = 0; ry < 4; ry++) {
        float4 u = *(const float4*)(xb + (size_t)(2 * ry) * WW);
        float4 w = *(const float4*)(xb + (size_t)(2 * ry + 1) * WW);
        float h, v, dd;
        haar_fwd(u.x, u.y, w.x, w.y, a1_0[ry], h, v, dd);
        h1_0[ry] = h * g1h; v1_0[ry] = v * g1v; d1_0[ry] = dd * g1d;
        haar_fwd(u.z, u.w, w.z, w.w, a1_1[ry], h, v, dd);
        h1_1[ry] = h * g1h; v1_1[ry] = v * g1v; d1_1[ry] = dd * g1d;
    }

    // ---- forward level 2 (gated) ----
    float a2[2], h2[2], v2[2], d2[2];
    #pragma unroll
    for (int ry2 = 0; ry2 < 2; ry2++) {
        float h, v, dd;
        haar_fwd(a1_0[2*ry2], a1_1[2*ry2], a1_0[2*ry2+1], a1_1[2*ry2+1],
                 a2[ry2], h, v, dd);
        h2[ry2] = h * g2h; v2[ry2] = v * g2v; d2[ry2] = dd * g2d;
    }

    // ---- level 3: symmetric in both lanes of the pair ----
    float R2[2];
    {
        float pa0 = __shfl_xor_sync(0xFFFFFFFFu, a2[0], 1);
        float pa1 = __shfl_xor_sync(0xFFFFFFFFu, a2[1], 1);
        bool odd = (g & 1);
        float lo0 = odd ? pa0 : a2[0], hi0 = odd ? a2[0] : pa0;
        float lo1 = odd ? pa1 : a2[1], hi1 = odd ? a2[1] : pa1;
        float a, h, v, dd;
        haar_fwd(lo0, hi0, lo1, hi1, a, h, v, dd);
        a *= aw; h *= g3h; v *= g3v; dd *= g3d;
        float x00, x01, x10, x11;
        haar_inv(a, h, v, dd, x00, x01, x10, x11);
        R2[0] = odd ? x01 : x00;
        R2[1] = odd ? x11 : x10;
    }

    // ---- inverse level 2 ----
    float r1_0[4], r1_1[4];
    #pragma unroll
    for (int ry2 = 0; ry2 < 2; ry2++) {
        haar_inv(R2[ry2], h2[ry2], v2[ry2], d2[ry2],
                 r1_0[2*ry2], r1_1[2*ry2], r1_0[2*ry2+1], r1_1[2*ry2+1]);
    }

    // ---- inverse level 1 + coalesced float4 stores ----
    #pragma unroll
    for (int ry = 0; ry < 4; ry++) {
        float p00, p01, p10, p11, q00, q01, q10, q11;
        haar_inv(r1_0[ry], h1_0[ry], v1_0[ry], d1_0[ry], p00, p01, p10, p11);
        haar_inv(r1_1[ry], h1_1[ry], v1_1[ry], d1_1[ry], q00, q01, q10, q11);
        *(float4*)(ob + (size_t)(2 * ry) * WW)     = make_float4(p00, p01, q00, q01);
        *(float4*)(ob + (size_t)(2 * ry + 1) * WW) = make_float4(p10, p11, q10, q11);
    }
}

// ---------------------------------------------------------------------------
extern "C" void kernel_launch(void* const* d_in, const int* in_sizes, int n_in,
                              void* d_out, int out_size) {
    const float* x   = (const float*)d_in[0];
    const float* Wa  = (const float*)d_in[1];
    const float* ba  = (const float*)d_in[2];
    const float* Wd1 = (const float*)d_in[3];
    const float* bd1 = (const float*)d_in[4];
    const float* Wd2 = (const float*)d_in[5];
    const float* bd2 = (const float*)d_in[6];
    const float* Wd3 = (const float*)d_in[7];
    const float* bd3 = (const float*)d_in[8];
    float* out = (float*)d_out;

    k_forward<<<dim3(FWD_BLOCKS, NB / 2), 256>>>(x, Wa, Wd1, Wd2, Wd3,
                                                 ba, bd1, bd2, bd3);
    k_recon<<<dim3(128, NB), 256>>>(x, out);
}